// round 4
// baseline (speedup 1.0000x reference)
#include <cuda_runtime.h>

// Problem constants (fixed by the reference: B=4, C=8, H=W=1024, R=1 cross kernel, wrap pad)
constexpr int Hh = 1024;
constexpr int Ww = 1024;
constexpr int PLANE = Hh * Ww;          // 1,048,576
constexpr int W8 = Ww / 8;              // 128 8-pixel groups per row

// Accurate fp32 exp (Cody-Waite reduction + cephes degree-6 poly, ~1 ulp).
// Immune to -use_fast_math rewriting of expf; only FMAs + one int bit-trick scale.
__device__ __forceinline__ float exp_acc(float x) {
    x = fminf(fmaxf(x, -87.3f), 88.0f);
    float n = rintf(x * 1.44269504088896341f);
    float r = fmaf(n, -0.693359375f, x);        // Cody-Waite hi
    r = fmaf(n, 2.12194440e-4f, r);             // Cody-Waite lo
    float rr = r * r;
    float y = 1.9875691500e-4f;
    y = fmaf(y, r, 1.3981999507e-3f);
    y = fmaf(y, r, 8.3334519073e-3f);
    y = fmaf(y, r, 4.1665795894e-2f);
    y = fmaf(y, r, 1.6666665459e-1f);
    y = fmaf(y, r, 5.0000001201e-1f);
    y = fmaf(y, rr, r);
    y = y + 1.0f;
    float sc = __int_as_float(((int)n + 127) << 23);
    return y * sc;
}

__device__ __forceinline__ float flip_one(float s, float J, float bf, float r, bool drop) {
    float de = 2.0f * s * J;
    bool flip;
    if (de <= 0.0f) {
        flip = drop;                            // p = 1, rand in [0,1) < 1 always
    } else {
        float p = exp_acc(-de * bf);
        flip = (r < p) && drop;
    }
    return flip ? -s : s;
}

__device__ __forceinline__ float4 ld_cs4(const float* p) {
    return __ldcs(reinterpret_cast<const float4*>(p));
}

__global__ __launch_bounds__(256, 6) void ising_step_kernel(
    const float* __restrict__ x,      // (4, 9, 1024, 1024): s = ch 0..7, b = ch 8
    const float* __restrict__ rnd,    // (4, 8, 1024, 1024)
    const float* __restrict__ drop,   // (1024, 1024)
    float* __restrict__ out)          // (4, 9, 1024, 1024)
{
    int tid = blockIdx.x * blockDim.x + threadIdx.x;   // 0 .. 4*1024*128-1
    int w8 = tid & (W8 - 1);
    int h  = (tid >> 7) & (Hh - 1);
    int b  = tid >> 17;
    int w  = w8 * 8;

    int rowc = h * Ww + w;                                  // this thread's 8 pixels
    int du = (((h + Hh - 1) & (Hh - 1)) - h) * Ww;          // relative offset: up row (wrap)
    int dd = (((h + 1) & (Hh - 1)) - h) * Ww;               // relative offset: down row (wrap)
    int dl = ((w + Ww - 1) & (Ww - 1)) - w;                 // relative: left of pixel 0 (wrap)
    int dr_ = ((w + 8) & (Ww - 1)) - w;                     // relative: right of pixel 7 (wrap)

    const float* xb = x + b * 9 * PLANE + rowc;

    // Pass 1: accumulate J (channel-summed cross-neighbor sum) for 8 pixels.
    // 6 independent vector loads + 2 independent scalar loads per channel -> high MLP.
    float J0 = 0.f, J1 = 0.f, J2 = 0.f, J3 = 0.f, J4 = 0.f, J5 = 0.f, J6 = 0.f, J7 = 0.f;
    {
        const float* sp = xb;
        #pragma unroll
        for (int c = 0; c < 8; c++, sp += PLANE) {
            float4 ca = *reinterpret_cast<const float4*>(sp);      // centers: stay in L1 for pass 2
            float4 cb = *reinterpret_cast<const float4*>(sp + 4);
            float4 u0 = ld_cs4(sp + du);                           // read-once streams
            float4 u1 = ld_cs4(sp + du + 4);
            float4 n0 = ld_cs4(sp + dd);
            float4 n1 = ld_cs4(sp + dd + 4);
            float lf = sp[dl];                                     // neighbor-thread centers: default policy
            float rt = sp[dr_];
            J0 += (u0.x + n0.x) + (lf   + ca.y);
            J1 += (u0.y + n0.y) + (ca.x + ca.z);
            J2 += (u0.z + n0.z) + (ca.y + ca.w);
            J3 += (u0.w + n0.w) + (ca.z + cb.x);
            J4 += (u1.x + n1.x) + (ca.w + cb.y);
            J5 += (u1.y + n1.y) + (cb.x + cb.z);
            J6 += (u1.z + n1.z) + (cb.y + cb.w);
            J7 += (u1.w + n1.w) + (cb.z + rt);
        }
    }

    // Field b and dropout mask for these 8 pixels
    float4 bfa = *reinterpret_cast<const float4*>(xb + 8 * PLANE);
    float4 bfb = *reinterpret_cast<const float4*>(xb + 8 * PLANE + 4);
    float4 da = ld_cs4(drop + rowc);
    float4 db = ld_cs4(drop + rowc + 4);
    bool m0 = da.x > 0.5f, m1 = da.y > 0.5f, m2 = da.z > 0.5f, m3 = da.w > 0.5f;
    bool m4 = db.x > 0.5f, m5 = db.y > 0.5f, m6 = db.z > 0.5f, m7 = db.w > 0.5f;

    float* ob = out + b * 9 * PLANE + rowc;
    // Pass-through channel 8 (the field)
    *reinterpret_cast<float4*>(ob + 8 * PLANE) = bfa;
    *reinterpret_cast<float4*>(ob + 8 * PLANE + 4) = bfb;

    const float* rb = rnd + b * 8 * PLANE + rowc;
    {
        const float* sp = xb;
        float* op = ob;
        const float* rp = rb;
        #pragma unroll
        for (int c = 0; c < 8; c++, sp += PLANE, op += PLANE, rp += PLANE) {
            float4 ca = *reinterpret_cast<const float4*>(sp);      // L1 hits (loaded in pass 1)
            float4 cb = *reinterpret_cast<const float4*>(sp + 4);
            float4 ra = ld_cs4(rp);                                // read-once streams
            float4 rv = ld_cs4(rp + 4);
            float4 oa, obv;
            oa.x  = flip_one(ca.x, J0, bfa.x, ra.x, m0);
            oa.y  = flip_one(ca.y, J1, bfa.y, ra.y, m1);
            oa.z  = flip_one(ca.z, J2, bfa.z, ra.z, m2);
            oa.w  = flip_one(ca.w, J3, bfa.w, ra.w, m3);
            obv.x = flip_one(cb.x, J4, bfb.x, rv.x, m4);
            obv.y = flip_one(cb.y, J5, bfb.y, rv.y, m5);
            obv.z = flip_one(cb.z, J6, bfb.z, rv.z, m6);
            obv.w = flip_one(cb.w, J7, bfb.w, rv.w, m7);
            *reinterpret_cast<float4*>(op) = oa;
            *reinterpret_cast<float4*>(op + 4) = obv;
        }
    }
}

extern "C" void kernel_launch(void* const* d_in, const int* in_sizes, int n_in,
                              void* d_out, int out_size) {
    const float* x    = (const float*)d_in[0];   // (4,9,1024,1024)
    const float* rnd  = (const float*)d_in[1];   // (4,8,1024,1024)
    const float* drop = (const float*)d_in[2];   // (1024,1024)
    // d_in[3] = nn_kernel: fixed cross structure, baked into the kernel
    float* out = (float*)d_out;

    int total_threads = 4 * Hh * W8;             // 524,288
    int block = 256;
    int grid = total_threads / block;            // 2048
    ising_step_kernel<<<grid, block>>>(x, rnd, drop, out);
}